// round 1
// baseline (speedup 1.0000x reference)
#include <cuda_runtime.h>
#include <math.h>

// Problem constants
#define BN 64
#define NN 325
#define TT 24
#define FF 64
#define HH 64
#define EE 2600
#define GG (BN*TT)   // 1536 graphs
#define NEG 0.2f

// CSR (dst-sorted) built once per launch by preprocess kernel
__device__ int g_off[NN + 1];
__device__ int g_src[EE];

// ---------------------------------------------------------------------------
// Preprocess: deterministic counting-sort of edges by dst into CSR.
// Single block; edge order within each dst segment = original edge order.
// ---------------------------------------------------------------------------
__global__ void preprocess_kernel(const int* __restrict__ ei) {
    __shared__ int s_dst[EE];
    __shared__ int s_cnt[NN];
    __shared__ int s_off[NN + 1];
    const int tid = threadIdx.x;

    for (int e = tid; e < EE; e += blockDim.x) s_dst[e] = ei[EE + e];
    __syncthreads();

    for (int n = tid; n < NN; n += blockDim.x) {
        int c = 0;
        for (int e = 0; e < EE; e++) c += (s_dst[e] == n);
        s_cnt[n] = c;
    }
    __syncthreads();

    if (tid == 0) {
        int run = 0;
        for (int n = 0; n < NN; n++) { s_off[n] = run; run += s_cnt[n]; }
        s_off[NN] = run;
    }
    __syncthreads();

    for (int n = tid; n <= NN; n += blockDim.x) g_off[n] = s_off[n];

    // Stable fill: thread-per-dst scans edges in order (deterministic)
    for (int n = tid; n < NN; n += blockDim.x) {
        int k = s_off[n];
        for (int e = 0; e < EE; e++) {
            if (s_dst[e] == n) { g_src[k++] = ei[e]; }
        }
    }
}

// ---------------------------------------------------------------------------
// Shared-memory layout (float offsets)
// ---------------------------------------------------------------------------
#define SM_H      0                         // h[N][64]          : 20800
#define SM_WT     (NN*64)                   // Wt[64][66] padded : 4224
#define SM_STAGE  (SM_WT + 64*66)           // stage[8w][8r][64f] dup-packed : 8192
#define SM_AS     (SM_STAGE + 8*8*64*2)     // a_s[N]
#define SM_AD     (SM_AS + NN)              // a_d[N]
#define SM_ALPHA  (SM_AD + NN)              // alpha[E]
#define SM_ATTS   (SM_ALPHA + EE)           // att_src[64]
#define SM_ATTD   (SM_ATTS + 64)            // att_dst[64]
#define SM_SRC    (SM_ATTD + 64)            // int src[E]
#define SM_OFF    (SM_SRC + EE)             // int off[N+1]
#define SM_FLOATS (SM_OFF + NN + 2)

__device__ __forceinline__ unsigned long long pack2(float x) {
    unsigned int b = __float_as_uint(x);
    return ((unsigned long long)b << 32) | (unsigned long long)b;
}
__device__ __forceinline__ void ffma2(unsigned long long& d,
                                      unsigned long long a,
                                      unsigned long long b) {
    // Blackwell packed fp32 pair FMA: d = a*b + d (elementwise on 2 floats)
    asm("fma.rn.f32x2 %0, %1, %2, %0;" : "+l"(d) : "l"(a), "l"(b));
}

// ---------------------------------------------------------------------------
// Main fused kernel: one CTA per graph g = b*T + t
// ---------------------------------------------------------------------------
__global__ __launch_bounds__(256, 1)
void gat_fused_kernel(const float* __restrict__ x,
                      const float* __restrict__ W,
                      const float* __restrict__ att_src,
                      const float* __restrict__ att_dst,
                      const float* __restrict__ bias,
                      float* __restrict__ out) {
    extern __shared__ float smem[];
    float* sh     = smem + SM_H;
    float* swt    = smem + SM_WT;
    float* sstage = smem + SM_STAGE;
    float* sas    = smem + SM_AS;
    float* sad    = smem + SM_AD;
    float* salpha = smem + SM_ALPHA;
    float* satts  = smem + SM_ATTS;
    float* sattd  = smem + SM_ATTD;
    int*   ssrc   = (int*)(smem + SM_SRC);
    int*   soff   = (int*)(smem + SM_OFF);

    const int tid = threadIdx.x;
    const int w   = tid >> 5;
    const int l   = tid & 31;
    const int g   = blockIdx.x;
    const int b   = g / TT;
    const int t   = g % TT;

    // ---- load W transposed (Wt[f][hh], stride 66 to dodge bank conflicts,
    //      keeps float2 alignment since 66*4 = 264 ≡ 0 mod 8)
    for (int i = tid; i < 64 * 64; i += 256) {
        int hh = i >> 6, f = i & 63;
        swt[f * 66 + hh] = W[i];
    }
    if (tid < 64) { satts[tid] = att_src[tid]; sattd[tid] = att_dst[tid]; }
    for (int i = tid; i < EE; i += 256)  ssrc[i] = g_src[i];
    for (int i = tid; i <= NN; i += 256) soff[i] = g_off[i];
    const float2 bias2 = *(const float2*)(bias + 2 * l);
    __syncthreads();

    // =======================================================================
    // Phase 1: h = x_g @ W^T   (x[b,n,t,f] -> row n at xbase + n*T*F)
    // warp-private 8-row tiles, lane covers output cols {2l, 2l+1}
    // =======================================================================
    const size_t xbase = (size_t)b * NN * (TT * FF) + (size_t)t * FF;

    float2 xv[8];
    {
        const int r0 = w * 8;
        #pragma unroll
        for (int r = 0; r < 8; r++) {
            int row = r0 + r;
            xv[r] = (row < NN)
                ? *(const float2*)(x + xbase + (size_t)row * (TT * FF) + 2 * l)
                : make_float2(0.f, 0.f);
        }
    }

    unsigned long long* stg_u = (unsigned long long*)sstage + (size_t)w * 8 * 64;
    float* stg_f = sstage + w * 8 * 128;

    for (int tile = w; tile < 41; tile += 8) {
        const int r0 = tile * 8;
        __syncwarp();
        // stage x tile duplicated-packed: ull slot f holds (x,x)
        #pragma unroll
        for (int r = 0; r < 8; r++) {
            float4 v = make_float4(xv[r].x, xv[r].x, xv[r].y, xv[r].y);
            *(float4*)(stg_f + r * 128 + 4 * l) = v;
        }
        __syncwarp();

        // prefetch next tile's x while we compute
        const int ntile = tile + 8;
        if (ntile < 41) {
            const int nr0 = ntile * 8;
            #pragma unroll
            for (int r = 0; r < 8; r++) {
                int row = nr0 + r;
                xv[r] = (row < NN)
                    ? *(const float2*)(x + xbase + (size_t)row * (TT * FF) + 2 * l)
                    : make_float2(0.f, 0.f);
            }
        }

        unsigned long long acc[8] = {0, 0, 0, 0, 0, 0, 0, 0};
        #pragma unroll 8
        for (int f = 0; f < 64; f++) {
            unsigned long long wv = *(unsigned long long*)(swt + f * 66 + 2 * l);
            #pragma unroll
            for (int r = 0; r < 8; r++)
                ffma2(acc[r], stg_u[r * 64 + f], wv);
        }

        #pragma unroll
        for (int r = 0; r < 8; r++) {
            int row = r0 + r;
            if (row < NN)
                *(unsigned long long*)(sh + row * 64 + 2 * l) = acc[r];
        }
    }
    __syncthreads();

    // =======================================================================
    // Phase 2: per-node attention logits  a_s = h.att_src, a_d = h.att_dst
    // =======================================================================
    for (int n = w; n < NN; n += 8) {
        float v0 = sh[n * 64 + l];
        float v1 = sh[n * 64 + 32 + l];
        float ps = v0 * satts[l] + v1 * satts[32 + l];
        float pd = v0 * sattd[l] + v1 * sattd[32 + l];
        #pragma unroll
        for (int o = 16; o > 0; o >>= 1) {
            ps += __shfl_xor_sync(0xffffffffu, ps, o);
            pd += __shfl_xor_sync(0xffffffffu, pd, o);
        }
        if (l == 0) { sas[n] = ps; sad[n] = pd; }
    }
    __syncthreads();

    // =======================================================================
    // Phase 3: per-dst segment softmax over CSR edges (thread per dst)
    // =======================================================================
    for (int d = tid; d < NN; d += 256) {
        const int beg = soff[d], end = soff[d + 1];
        const float ad = sad[d];
        float m = -3.4e38f;
        for (int i = beg; i < end; i++) {
            float s = sas[ssrc[i]] + ad;
            s = (s > 0.f) ? s : NEG * s;      // leaky_relu
            salpha[i] = s;
            m = fmaxf(m, s);
        }
        float den = 0.f;
        for (int i = beg; i < end; i++) {
            float ex = __expf(salpha[i] - m);
            salpha[i] = ex;
            den += ex;
        }
        float inv = 1.f / den;                 // unused if segment empty
        for (int i = beg; i < end; i++) salpha[i] *= inv;
    }
    __syncthreads();

    // =======================================================================
    // Phase 4: aggregate alpha*h[src] per dst, + bias, exact GELU, store.
    // warp per dst; lane covers cols {2l, 2l+1}; fully coalesced stores.
    // Output flat order is (b, t, n, h) — the reference reshape is a raw view.
    // =======================================================================
    float* outg = out + (size_t)g * NN * 64;
    for (int d = w; d < NN; d += 8) {
        const int beg = soff[d], end = soff[d + 1];
        unsigned long long acc = 0;
        for (int i = beg; i < end; i++) {
            int s = ssrc[i];                       // broadcast LDS
            unsigned long long av = pack2(salpha[i]);
            unsigned long long hv = *(unsigned long long*)(sh + s * 64 + 2 * l);
            ffma2(acc, av, hv);
        }
        float vx = __uint_as_float((unsigned)(acc & 0xffffffffu)) + bias2.x;
        float vy = __uint_as_float((unsigned)(acc >> 32)) + bias2.y;
        float gx = 0.5f * vx * (1.f + erff(vx * 0.70710678118654752f));
        float gy = 0.5f * vy * (1.f + erff(vy * 0.70710678118654752f));
        *(float2*)(outg + d * 64 + 2 * l) = make_float2(gx, gy);
    }
}

// ---------------------------------------------------------------------------
// Launch
// Inputs (metadata order): x f32[64,325,24,64], edge_index i32[2,2600],
//   W f32[64,64], att_src f32[64], att_dst f32[64], bias f32[64]
// Output: f32, flat (b,t,n,h) order, 31,948,800 elements
// ---------------------------------------------------------------------------
extern "C" void kernel_launch(void* const* d_in, const int* in_sizes, int n_in,
                              void* d_out, int out_size) {
    const float* x    = (const float*)d_in[0];
    const int*   ei   = (const int*)d_in[1];
    const float* W    = (const float*)d_in[2];
    const float* atts = (const float*)d_in[3];
    const float* attd = (const float*)d_in[4];
    const float* bias = (const float*)d_in[5];
    float* out = (float*)d_out;

    const size_t smem_bytes = (size_t)SM_FLOATS * sizeof(float);
    cudaFuncSetAttribute(gat_fused_kernel,
                         cudaFuncAttributeMaxDynamicSharedMemorySize,
                         (int)smem_bytes);

    preprocess_kernel<<<1, 384>>>(ei);
    gat_fused_kernel<<<GG, 256, smem_bytes>>>(x, W, atts, attd, bias, out);
}